// round 1
// baseline (speedup 1.0000x reference)
#include <cuda_runtime.h>

#define T_STEPS 1000
#define BATCH   512
#define NIN     128
#define HPAD    256
#define LANES   (BATCH * HPAD)        // 131072
#define MROWS   (T_STEPS * BATCH)     // 512000
#define OUTB    (T_STEPS * BATCH * 2) // 1024000

// ---- scratch (static device memory; no allocations allowed) ----
__device__ float g_buf1[(size_t)MROWS * HPAD];  // cur1 -> s1 (in place)
__device__ float g_buf2[(size_t)MROWS * HPAD];  // cur2 -> s2 (in place)
__device__ float g_cur3[(size_t)MROWS * 2];
__device__ float g_W1p[NIN * HPAD];
__device__ float g_W2p[HPAD * HPAD];
__device__ float g_b1p[HPAD];
__device__ float g_b2p[HPAD];

// ---- pad weights/biases to HPAD=256 with zeros ----
__global__ void prep_kernel(const float* __restrict__ W1, const float* __restrict__ b1,
                            const float* __restrict__ W2, const float* __restrict__ b2) {
    int i = blockIdx.x * blockDim.x + threadIdx.x;  // 0..65535
    int k = i >> 8, n = i & 255;
    if (i < NIN * HPAD)
        g_W1p[i] = (n < 250) ? W1[k * 250 + n] : 0.0f;
    g_W2p[i] = (k < 250 && n < 250) ? W2[k * 250 + n] : 0.0f;
    if (i < HPAD) {
        g_b1p[i] = (i < 250) ? b1[i] : 0.0f;
        g_b2p[i] = (i < 250) ? b2[i] : 0.0f;
    }
}

// ---- fp32 SGEMM: C[M,256] = A[M,K] @ W[K,256] + bias, BM=BN=128, BK=8 ----
#define BM 128
#define BN 128
#define BKK 8

__global__ __launch_bounds__(256, 2)
void sgemm_kernel(const float* __restrict__ A, const float* __restrict__ W,
                  const float* __restrict__ bias, float* __restrict__ C, int K) {
    __shared__ __align__(16) float As[BKK][BM];
    __shared__ __align__(16) float Ws[BKK][BN];

    const int tid = threadIdx.x;
    const size_t m0 = (size_t)blockIdx.x * BM;
    const int n0 = blockIdx.y * BN;
    const int tr = tid >> 4;   // 0..15
    const int tc = tid & 15;   // 0..15

    const int aRow = tid >> 1;           // 0..127
    const int aCol = (tid & 1) * 4;      // 0 or 4
    const int wRow = tid >> 5;           // 0..7
    const int wCol = (tid & 31) * 4;     // 0..124

    float acc[8][8];
#pragma unroll
    for (int i = 0; i < 8; i++)
#pragma unroll
        for (int j = 0; j < 8; j++) acc[i][j] = 0.0f;

    const float* Abase = A + (m0 + aRow) * (size_t)K;

    for (int k0 = 0; k0 < K; k0 += BKK) {
        float4 av = *(const float4*)(Abase + k0 + aCol);
        As[aCol + 0][aRow] = av.x;
        As[aCol + 1][aRow] = av.y;
        As[aCol + 2][aRow] = av.z;
        As[aCol + 3][aRow] = av.w;
        float4 wv = *(const float4*)(W + (size_t)(k0 + wRow) * HPAD + n0 + wCol);
        *(float4*)(&Ws[wRow][wCol]) = wv;
        __syncthreads();
#pragma unroll
        for (int k = 0; k < BKK; k++) {
            float ra[8], rb[8];
            *(float4*)(&ra[0]) = *(const float4*)(&As[k][tr * 8]);
            *(float4*)(&ra[4]) = *(const float4*)(&As[k][tr * 8 + 4]);
            *(float4*)(&rb[0]) = *(const float4*)(&Ws[k][tc * 8]);
            *(float4*)(&rb[4]) = *(const float4*)(&Ws[k][tc * 8 + 4]);
#pragma unroll
            for (int i = 0; i < 8; i++)
#pragma unroll
                for (int j = 0; j < 8; j++)
                    acc[i][j] = fmaf(ra[i], rb[j], acc[i][j]);
        }
        __syncthreads();
    }

#pragma unroll
    for (int i = 0; i < 8; i++) {
        size_t rowOff = (m0 + tr * 8 + i) * (size_t)HPAD;
#pragma unroll
        for (int j = 0; j < 8; j += 4) {
            int n = n0 + tc * 8 + j;
            float4 bv = *(const float4*)(bias + n);
            float4 cv;
            cv.x = acc[i][j + 0] + bv.x;
            cv.y = acc[i][j + 1] + bv.y;
            cv.z = acc[i][j + 2] + bv.z;
            cv.w = acc[i][j + 3] + bv.w;
            *(float4*)(C + rowOff + n) = cv;
        }
    }
}

// ---- LIF scan for layers 1/2: in-place cur -> spike, one lane per (b,h) ----
__global__ void lif_scan_kernel(float* __restrict__ buf) {
    int lane = blockIdx.x * blockDim.x + threadIdx.x;  // 0..131071
    float m = 0.0f;
    size_t idx = lane;
#pragma unroll 8
    for (int t = 0; t < T_STEPS; t++) {
        float cur = buf[idx];
        float r = (m > 1.0f) ? 1.0f : 0.0f;
        // match reference association: ((beta*m) + cur) - reset
        m = __fadd_rn(__fadd_rn(__fmul_rn(0.9f, m), cur), -r);
        buf[idx] = (m > 1.0f) ? 1.0f : 0.0f;
        idx += LANES;
    }
}

// ---- layer 3 GEMM: warp-per-row dot, N=2, K=250 (s2 padded cols are exactly 0) ----
__global__ __launch_bounds__(256)
void gemm3_kernel(const float* __restrict__ S2, const float* __restrict__ W3,
                  const float* __restrict__ b3, float* __restrict__ cur3) {
    __shared__ float w0[HPAD], w1[HPAD];
    int tid = threadIdx.x;
    if (tid < 250) { w0[tid] = W3[tid * 2]; w1[tid] = W3[tid * 2 + 1]; }
    else           { w0[tid] = 0.0f;        w1[tid] = 0.0f; }
    __syncthreads();

    int warp = tid >> 5, lane = tid & 31;
    size_t row = (size_t)blockIdx.x * 8 + warp;
    const float4* p = (const float4*)(S2 + row * HPAD);
    float a0 = 0.0f, a1 = 0.0f;
#pragma unroll
    for (int i = 0; i < 2; i++) {
        float4 v = p[lane * 2 + i];
        int k = (lane * 2 + i) * 4;
        a0 = fmaf(v.x, w0[k], a0); a0 = fmaf(v.y, w0[k + 1], a0);
        a0 = fmaf(v.z, w0[k + 2], a0); a0 = fmaf(v.w, w0[k + 3], a0);
        a1 = fmaf(v.x, w1[k], a1); a1 = fmaf(v.y, w1[k + 1], a1);
        a1 = fmaf(v.z, w1[k + 2], a1); a1 = fmaf(v.w, w1[k + 3], a1);
    }
#pragma unroll
    for (int off = 16; off; off >>= 1) {
        a0 += __shfl_xor_sync(0xffffffffu, a0, off);
        a1 += __shfl_xor_sync(0xffffffffu, a1, off);
    }
    if (lane == 0) {
        cur3[row * 2 + 0] = a0 + b3[0];
        cur3[row * 2 + 1] = a1 + b3[1];
    }
}

// ---- LIF scan for layer 3 + output write (spikes then mem_rec) ----
__global__ void lif3_kernel(const float* __restrict__ cur3, float* __restrict__ out) {
    int lane = blockIdx.x * blockDim.x + threadIdx.x;  // 0..1023 = b*2+o
    float m = 0.0f;
#pragma unroll 8
    for (int t = 0; t < T_STEPS; t++) {
        float cur = cur3[t * 1024 + lane];
        float r = (m > 1.0f) ? 1.0f : 0.0f;
        m = __fadd_rn(__fadd_rn(__fmul_rn(0.9f, m), cur), -r);
        out[t * 1024 + lane] = (m > 1.0f) ? 1.0f : 0.0f;  // spikes [T,B,2]
        out[OUTB + t * 1024 + lane] = m;                  // mem_rec [T,B,2]
    }
}

extern "C" void kernel_launch(void* const* d_in, const int* in_sizes, int n_in,
                              void* d_out, int out_size) {
    const float* x  = (const float*)d_in[0];
    const float* W1 = (const float*)d_in[1];
    const float* b1 = (const float*)d_in[2];
    const float* W2 = (const float*)d_in[3];
    const float* b2 = (const float*)d_in[4];
    const float* W3 = (const float*)d_in[5];
    const float* b3 = (const float*)d_in[6];
    float* out = (float*)d_out;

    float *buf1, *buf2, *cur3, *W1p, *W2p, *b1p, *b2p;
    cudaGetSymbolAddress((void**)&buf1, g_buf1);
    cudaGetSymbolAddress((void**)&buf2, g_buf2);
    cudaGetSymbolAddress((void**)&cur3, g_cur3);
    cudaGetSymbolAddress((void**)&W1p, g_W1p);
    cudaGetSymbolAddress((void**)&W2p, g_W2p);
    cudaGetSymbolAddress((void**)&b1p, g_b1p);
    cudaGetSymbolAddress((void**)&b2p, g_b2p);

    prep_kernel<<<256, 256>>>(W1, b1, W2, b2);

    // layer 1: cur1 = x @ W1 + b1   [512000,128]@[128,256]
    sgemm_kernel<<<dim3(MROWS / BM, HPAD / BN), 256>>>(x, W1p, b1p, buf1, NIN);
    lif_scan_kernel<<<LANES / 256, 256>>>(buf1);

    // layer 2: cur2 = s1 @ W2 + b2  [512000,256]@[256,256]
    sgemm_kernel<<<dim3(MROWS / BM, HPAD / BN), 256>>>(buf1, W2p, b2p, buf2, HPAD);
    lif_scan_kernel<<<LANES / 256, 256>>>(buf2);

    // layer 3: cur3 = s2 @ W3 + b3, then scan + write outputs
    gemm3_kernel<<<MROWS / 8, 256>>>(buf2, W3, b3, cur3);
    lif3_kernel<<<4, 256>>>(cur3, out);
}

// round 3
// speedup vs baseline: 1.1876x; 1.1876x over previous
#include <cuda_runtime.h>

#define T_STEPS 1000
#define BATCH   512
#define NIN     128
#define HPAD    256
#define LANES   (BATCH * HPAD)        // 131072
#define MROWS   (T_STEPS * BATCH)     // 512000
#define OUTB    (T_STEPS * BATCH * 2) // 1024000

// ---- scratch (static device memory; no allocations allowed) ----
__device__ float g_buf1[(size_t)MROWS * HPAD];  // cur1 -> s1 (in place)
__device__ float g_buf2[(size_t)MROWS * HPAD];  // cur2 -> s2 (in place)
__device__ float g_cur3[(size_t)MROWS * 2];
__device__ float g_W1p[NIN * HPAD];
__device__ float g_W2p[HPAD * HPAD];
__device__ float g_b1p[HPAD];
__device__ float g_b2p[HPAD];

// ---- pad weights/biases to HPAD=256 with zeros ----
__global__ void prep_kernel(const float* __restrict__ W1, const float* __restrict__ b1,
                            const float* __restrict__ W2, const float* __restrict__ b2) {
    int i = blockIdx.x * blockDim.x + threadIdx.x;  // 0..65535
    int k = i >> 8, n = i & 255;
    if (i < NIN * HPAD)
        g_W1p[i] = (n < 250) ? W1[k * 250 + n] : 0.0f;
    g_W2p[i] = (k < 250 && n < 250) ? W2[k * 250 + n] : 0.0f;
    if (i < HPAD) {
        g_b1p[i] = (i < 250) ? b1[i] : 0.0f;
        g_b2p[i] = (i < 250) ? b2[i] : 0.0f;
    }
}

// ---- packed f32x2 helpers ----
__device__ __forceinline__ void ffma2(unsigned long long& d, unsigned long long a,
                                      unsigned long long b) {
    asm("fma.rn.f32x2 %0, %1, %2, %0;" : "+l"(d) : "l"(a), "l"(b));
}
__device__ __forceinline__ unsigned long long dup2(float v) {
    unsigned long long r;
    unsigned int u = __float_as_uint(v);
    asm("mov.b64 %0, {%1, %1};" : "=l"(r) : "r"(u));
    return r;
}
__device__ __forceinline__ float2 unpack2(unsigned long long v) {
    float2 f;
    asm("mov.b64 {%0, %1}, %2;" : "=f"(f.x), "=f"(f.y) : "l"(v));
    return f;
}

// ---- fp32 SGEMM via packed fma.rn.f32x2: C[M,256] = A[M,K] @ W[K,256] + bias ----
#define BM 128
#define BN 128
#define BK 16

__global__ __launch_bounds__(256, 2)
void sgemm_kernel(const float* __restrict__ A, const float* __restrict__ W,
                  const float* __restrict__ bias, float* __restrict__ C, int K) {
    __shared__ __align__(16) float As[BK][BM];
    __shared__ __align__(16) float Ws[BK][BN];

    const int tid = threadIdx.x;
    const size_t m0 = (size_t)blockIdx.x * BM;
    const int n0 = blockIdx.y * BN;
    const int tr = tid >> 4;   // 0..15 : output rows tr*8 .. tr*8+7
    const int tc = tid & 15;   // output cols tc*4..tc*4+3 and 64+tc*4..64+tc*4+3

    const int aRow = tid >> 1;          // 0..127
    const int aCol = (tid & 1) * 8;     // 0 or 8
    const int wRow = tid >> 4;          // 0..15
    const int wCol = (tid & 15) * 8;    // 0..120

    unsigned long long acc[8][4];
#pragma unroll
    for (int i = 0; i < 8; i++)
#pragma unroll
        for (int jj = 0; jj < 4; jj++) acc[i][jj] = 0ULL;

    const float* Abase = A + (m0 + aRow) * (size_t)K;
    const float* Wbase = W + (size_t)wRow * HPAD + n0 + wCol;

    for (int k0 = 0; k0 < K; k0 += BK) {
        float4 av0 = *(const float4*)(Abase + k0 + aCol);
        float4 av1 = *(const float4*)(Abase + k0 + aCol + 4);
        As[aCol + 0][aRow] = av0.x;
        As[aCol + 1][aRow] = av0.y;
        As[aCol + 2][aRow] = av0.z;
        As[aCol + 3][aRow] = av0.w;
        As[aCol + 4][aRow] = av1.x;
        As[aCol + 5][aRow] = av1.y;
        As[aCol + 6][aRow] = av1.z;
        As[aCol + 7][aRow] = av1.w;
        float4 wv0 = *(const float4*)(Wbase + (size_t)k0 * HPAD);
        float4 wv1 = *(const float4*)(Wbase + (size_t)k0 * HPAD + 4);
        *(float4*)(&Ws[wRow][wCol]) = wv0;
        *(float4*)(&Ws[wRow][wCol + 4]) = wv1;
        __syncthreads();
#pragma unroll
        for (int k = 0; k < BK; k++) {
            float ra[8];
            *(float4*)(&ra[0]) = *(const float4*)(&As[k][tr * 8]);
            *(float4*)(&ra[4]) = *(const float4*)(&As[k][tr * 8 + 4]);
            unsigned long long rb[4];
            rb[0] = *(const unsigned long long*)(&Ws[k][tc * 4]);
            rb[1] = *(const unsigned long long*)(&Ws[k][tc * 4 + 2]);
            rb[2] = *(const unsigned long long*)(&Ws[k][64 + tc * 4]);
            rb[3] = *(const unsigned long long*)(&Ws[k][64 + tc * 4 + 2]);
#pragma unroll
            for (int i = 0; i < 8; i++) {
                unsigned long long aa = dup2(ra[i]);
                ffma2(acc[i][0], aa, rb[0]);
                ffma2(acc[i][1], aa, rb[1]);
                ffma2(acc[i][2], aa, rb[2]);
                ffma2(acc[i][3], aa, rb[3]);
            }
        }
        __syncthreads();
    }

    const int nA = n0 + tc * 4;
    const int nB = n0 + 64 + tc * 4;
    float4 bvA = *(const float4*)(bias + nA);
    float4 bvB = *(const float4*)(bias + nB);
#pragma unroll
    for (int i = 0; i < 8; i++) {
        size_t rowOff = (m0 + tr * 8 + i) * (size_t)HPAD;
        float2 p0 = unpack2(acc[i][0]);
        float2 p1 = unpack2(acc[i][1]);
        float2 p2 = unpack2(acc[i][2]);
        float2 p3 = unpack2(acc[i][3]);
        float4 cA = {p0.x + bvA.x, p0.y + bvA.y, p1.x + bvA.z, p1.y + bvA.w};
        float4 cB = {p2.x + bvB.x, p2.y + bvB.y, p3.x + bvB.z, p3.y + bvB.w};
        *(float4*)(C + rowOff + nA) = cA;
        *(float4*)(C + rowOff + nB) = cB;
    }
}

// ---- LIF scan for layers 1/2: in-place cur -> spike, one lane per (b,h) ----
__global__ void lif_scan_kernel(float* __restrict__ buf) {
    int lane = blockIdx.x * blockDim.x + threadIdx.x;  // 0..131071
    float m = 0.0f;
    size_t idx = lane;
#pragma unroll 8
    for (int t = 0; t < T_STEPS; t++) {
        float cur = buf[idx];
        float r = (m > 1.0f) ? 1.0f : 0.0f;
        // match reference association: ((beta*m) + cur) - reset
        m = __fadd_rn(__fadd_rn(__fmul_rn(0.9f, m), cur), -r);
        buf[idx] = (m > 1.0f) ? 1.0f : 0.0f;
        idx += LANES;
    }
}

// ---- layer 3 GEMM: warp-per-row dot, N=2, K=250 (s2 padded cols are exactly 0) ----
__global__ __launch_bounds__(256)
void gemm3_kernel(const float* __restrict__ S2, const float* __restrict__ W3,
                  const float* __restrict__ b3, float* __restrict__ cur3) {
    __shared__ float w0[HPAD], w1[HPAD];
    int tid = threadIdx.x;
    if (tid < 250) { w0[tid] = W3[tid * 2]; w1[tid] = W3[tid * 2 + 1]; }
    else           { w0[tid] = 0.0f;        w1[tid] = 0.0f; }
    __syncthreads();

    int warp = tid >> 5, lane = tid & 31;
    size_t row = (size_t)blockIdx.x * 8 + warp;
    const float4* p = (const float4*)(S2 + row * HPAD);
    float a0 = 0.0f, a1 = 0.0f;
#pragma unroll
    for (int i = 0; i < 2; i++) {
        float4 v = p[lane * 2 + i];
        int k = (lane * 2 + i) * 4;
        a0 = fmaf(v.x, w0[k], a0); a0 = fmaf(v.y, w0[k + 1], a0);
        a0 = fmaf(v.z, w0[k + 2], a0); a0 = fmaf(v.w, w0[k + 3], a0);
        a1 = fmaf(v.x, w1[k], a1); a1 = fmaf(v.y, w1[k + 1], a1);
        a1 = fmaf(v.z, w1[k + 2], a1); a1 = fmaf(v.w, w1[k + 3], a1);
    }
#pragma unroll
    for (int off = 16; off; off >>= 1) {
        a0 += __shfl_xor_sync(0xffffffffu, a0, off);
        a1 += __shfl_xor_sync(0xffffffffu, a1, off);
    }
    if (lane == 0) {
        cur3[row * 2 + 0] = a0 + b3[0];
        cur3[row * 2 + 1] = a1 + b3[1];
    }
}

// ---- LIF scan for layer 3 + output write (spikes then mem_rec) ----
__global__ void lif3_kernel(const float* __restrict__ cur3, float* __restrict__ out) {
    int lane = blockIdx.x * blockDim.x + threadIdx.x;  // 0..1023 = b*2+o
    float m = 0.0f;
#pragma unroll 8
    for (int t = 0; t < T_STEPS; t++) {
        float cur = cur3[t * 1024 + lane];
        float r = (m > 1.0f) ? 1.0f : 0.0f;
        m = __fadd_rn(__fadd_rn(__fmul_rn(0.9f, m), cur), -r);
        out[t * 1024 + lane] = (m > 1.0f) ? 1.0f : 0.0f;  // spikes [T,B,2]
        out[OUTB + t * 1024 + lane] = m;                  // mem_rec [T,B,2]
    }
}

extern "C" void kernel_launch(void* const* d_in, const int* in_sizes, int n_in,
                              void* d_out, int out_size) {
    const float* x  = (const float*)d_in[0];
    const float* W1 = (const float*)d_in[1];
    const float* b1 = (const float*)d_in[2];
    const float* W2 = (const float*)d_in[3];
    const float* b2 = (const float*)d_in[4];
    const float* W3 = (const float*)d_in[5];
    const float* b3 = (const float*)d_in[6];
    float* out = (float*)d_out;

    float *buf1, *buf2, *cur3, *W1p, *W2p, *b1p, *b2p;
    cudaGetSymbolAddress((void**)&buf1, g_buf1);
    cudaGetSymbolAddress((void**)&buf2, g_buf2);
    cudaGetSymbolAddress((void**)&cur3, g_cur3);
    cudaGetSymbolAddress((void**)&W1p, g_W1p);
    cudaGetSymbolAddress((void**)&W2p, g_W2p);
    cudaGetSymbolAddress((void**)&b1p, g_b1p);
    cudaGetSymbolAddress((void**)&b2p, g_b2p);

    prep_kernel<<<256, 256>>>(W1, b1, W2, b2);

    // layer 1: cur1 = x @ W1 + b1   [512000,128]@[128,256]
    sgemm_kernel<<<dim3(MROWS / BM, HPAD / BN), 256>>>(x, W1p, b1p, buf1, NIN);
    lif_scan_kernel<<<LANES / 256, 256>>>(buf1);

    // layer 2: cur2 = s1 @ W2 + b2  [512000,256]@[256,256]
    sgemm_kernel<<<dim3(MROWS / BM, HPAD / BN), 256>>>(buf1, W2p, b2p, buf2, HPAD);
    lif_scan_kernel<<<LANES / 256, 256>>>(buf2);

    // layer 3: cur3 = s2 @ W3 + b3, then scan + write outputs
    gemm3_kernel<<<MROWS / 8, 256>>>(buf2, W3, b3, cur3);
    lif3_kernel<<<4, 256>>>(cur3, out);
}

// round 6
// speedup vs baseline: 1.5675x; 1.3199x over previous
#include <cuda_runtime.h>
#include <cuda_bf16.h>
#include <cstdint>

#define T_STEPS 1000
#define BATCH   512
#define NIN     128
#define HPAD    256
#define KCAT    768                   // 3 bf16 splits x 256
#define LANES   (BATCH * HPAD)        // 131072
#define MROWS   (T_STEPS * BATCH)     // 512000
#define OUTB    (T_STEPS * BATCH * 2) // 1024000

// ---- scratch (static device memory; no allocations allowed) ----
__device__ float g_buf1[(size_t)MROWS * HPAD];          // cur1 (fp32)
__device__ __nv_bfloat16 g_s1b[(size_t)MROWS * HPAD];   // s1 spikes bf16
__device__ float g_buf2[(size_t)MROWS * HPAD];          // cur2 -> s2 (in place)
__device__ float g_cur3[(size_t)MROWS * 2];
__device__ float g_W1p[NIN * HPAD];
__device__ float g_b1p[HPAD];
__device__ float g_b2p[HPAD];
__device__ __nv_bfloat16 g_W2b[HPAD * KCAT];  // [n=256][k'=768], 3-split per katom

// ================= helpers =================
__device__ __forceinline__ uint32_t smem_u32(const void* p) {
    return (uint32_t)__cvta_generic_to_shared(p);
}
__device__ __forceinline__ void cpasync16(uint32_t dst, const void* src) {
    asm volatile("cp.async.cg.shared.global [%0], [%1], 16;" :: "r"(dst), "l"(src));
}
__device__ __forceinline__ uint32_t swz(uint32_t off) { return off ^ ((off >> 3) & 0x70); }
__device__ __forceinline__ uint32_t lds32(uint32_t addr) {
    uint32_t v;
    asm volatile("ld.shared.b32 %0, [%1];" : "=r"(v) : "r"(addr));
    return v;
}
__device__ __forceinline__ void mma_bf16(float* d, const uint32_t* a, const uint32_t* b) {
    asm volatile(
        "mma.sync.aligned.m16n8k16.row.col.f32.bf16.bf16.f32 "
        "{%0,%1,%2,%3}, {%4,%5,%6,%7}, {%8,%9}, {%0,%1,%2,%3};"
        : "+f"(d[0]), "+f"(d[1]), "+f"(d[2]), "+f"(d[3])
        : "r"(a[0]), "r"(a[1]), "r"(a[2]), "r"(a[3]), "r"(b[0]), "r"(b[1]));
}

// ================= prep kernels =================
__global__ void prep_kernel(const float* __restrict__ W1, const float* __restrict__ b1,
                            const float* __restrict__ b2) {
    int i = blockIdx.x * blockDim.x + threadIdx.x;  // 0..32767
    int k = i >> 8, n = i & 255;
    if (i < NIN * HPAD)
        g_W1p[i] = (n < 250) ? W1[k * 250 + n] : 0.0f;
    if (i < HPAD) {
        g_b1p[i] = (i < 250) ? b1[i] : 0.0f;
        g_b2p[i] = (i < 250) ? b2[i] : 0.0f;
    }
}
// W2b[n][c*64+kk] = split_{c%3}(W2[(c/3)*64+kk][n]), zero-padded
__global__ void prep_w2b_kernel(const float* __restrict__ W2) {
    int id = blockIdx.x * blockDim.x + threadIdx.x;  // 0..196607
    int n = id / KCAT, kp = id % KCAT;
    int c = kp >> 6, kk = kp & 63;
    int katom = c / 3, split = c % 3;
    int k = katom * 64 + kk;
    float w = (k < 250 && n < 250) ? W2[k * 250 + n] : 0.0f;
    __nv_bfloat16 hi = __float2bfloat16(w);
    float r1 = w - __bfloat162float(hi);
    __nv_bfloat16 mid = __float2bfloat16(r1);
    float r2 = r1 - __bfloat162float(mid);
    __nv_bfloat16 lo = __float2bfloat16(r2);
    g_W2b[id] = (split == 0) ? hi : (split == 1) ? mid : lo;
}

// ================= packed f32x2 helpers for layer-1 SGEMM =================
__device__ __forceinline__ void ffma2(unsigned long long& d, unsigned long long a,
                                      unsigned long long b) {
    asm("fma.rn.f32x2 %0, %1, %2, %0;" : "+l"(d) : "l"(a), "l"(b));
}
__device__ __forceinline__ unsigned long long dup2(float v) {
    unsigned long long r;
    unsigned int u = __float_as_uint(v);
    asm("mov.b64 %0, {%1, %1};" : "=l"(r) : "r"(u));
    return r;
}
__device__ __forceinline__ float2 unpack2(unsigned long long v) {
    float2 f;
    asm("mov.b64 {%0, %1}, %2;" : "=f"(f.x), "=f"(f.y) : "l"(v));
    return f;
}

// ---- layer-1 fp32 SGEMM (FFMA2), C[M,256] = A[M,128] @ W[128,256] + bias ----
#define BM 128
#define BN 128
#define BK 16
__global__ __launch_bounds__(256, 2)
void sgemm_kernel(const float* __restrict__ A, const float* __restrict__ W,
                  const float* __restrict__ bias, float* __restrict__ C, int K) {
    __shared__ __align__(16) float As[BK][BM];
    __shared__ __align__(16) float Ws[BK][BN];
    const int tid = threadIdx.x;
    const size_t m0 = (size_t)blockIdx.x * BM;
    const int n0 = blockIdx.y * BN;
    const int tr = tid >> 4, tc = tid & 15;
    const int aRow = tid >> 1, aCol = (tid & 1) * 8;
    const int wRow = tid >> 4, wCol = (tid & 15) * 8;

    unsigned long long acc[8][4];
#pragma unroll
    for (int i = 0; i < 8; i++)
#pragma unroll
        for (int jj = 0; jj < 4; jj++) acc[i][jj] = 0ULL;

    const float* Abase = A + (m0 + aRow) * (size_t)K;
    const float* Wbase = W + (size_t)wRow * HPAD + n0 + wCol;

    for (int k0 = 0; k0 < K; k0 += BK) {
        float4 av0 = *(const float4*)(Abase + k0 + aCol);
        float4 av1 = *(const float4*)(Abase + k0 + aCol + 4);
        As[aCol + 0][aRow] = av0.x; As[aCol + 1][aRow] = av0.y;
        As[aCol + 2][aRow] = av0.z; As[aCol + 3][aRow] = av0.w;
        As[aCol + 4][aRow] = av1.x; As[aCol + 5][aRow] = av1.y;
        As[aCol + 6][aRow] = av1.z; As[aCol + 7][aRow] = av1.w;
        float4 wv0 = *(const float4*)(Wbase + (size_t)k0 * HPAD);
        float4 wv1 = *(const float4*)(Wbase + (size_t)k0 * HPAD + 4);
        *(float4*)(&Ws[wRow][wCol]) = wv0;
        *(float4*)(&Ws[wRow][wCol + 4]) = wv1;
        __syncthreads();
#pragma unroll
        for (int k = 0; k < BK; k++) {
            float ra[8];
            *(float4*)(&ra[0]) = *(const float4*)(&As[k][tr * 8]);
            *(float4*)(&ra[4]) = *(const float4*)(&As[k][tr * 8 + 4]);
            unsigned long long rb[4];
            rb[0] = *(const unsigned long long*)(&Ws[k][tc * 4]);
            rb[1] = *(const unsigned long long*)(&Ws[k][tc * 4 + 2]);
            rb[2] = *(const unsigned long long*)(&Ws[k][64 + tc * 4]);
            rb[3] = *(const unsigned long long*)(&Ws[k][64 + tc * 4 + 2]);
#pragma unroll
            for (int i = 0; i < 8; i++) {
                unsigned long long aa = dup2(ra[i]);
                ffma2(acc[i][0], aa, rb[0]);
                ffma2(acc[i][1], aa, rb[1]);
                ffma2(acc[i][2], aa, rb[2]);
                ffma2(acc[i][3], aa, rb[3]);
            }
        }
        __syncthreads();
    }
    const int nA = n0 + tc * 4, nB = n0 + 64 + tc * 4;
    float4 bvA = *(const float4*)(bias + nA);
    float4 bvB = *(const float4*)(bias + nB);
#pragma unroll
    for (int i = 0; i < 8; i++) {
        size_t rowOff = (m0 + tr * 8 + i) * (size_t)HPAD;
        float2 p0 = unpack2(acc[i][0]), p1 = unpack2(acc[i][1]);
        float2 p2 = unpack2(acc[i][2]), p3 = unpack2(acc[i][3]);
        float4 cA = {p0.x + bvA.x, p0.y + bvA.y, p1.x + bvA.z, p1.y + bvA.w};
        float4 cB = {p2.x + bvB.x, p2.y + bvB.y, p3.x + bvB.z, p3.y + bvB.w};
        *(float4*)(C + rowOff + nA) = cA;
        *(float4*)(C + rowOff + nB) = cB;
    }
}

// ================= layer-2 GEMM via mma.sync bf16 (3-split, K=768) =================
// out[M,256] (raw, no bias) = s1b[M,256] @ W2cat ; grid (4000, 2), 256 thr
#define OFF_A0 0
#define OFF_A1 16384
#define OFF_B0 32768
#define OFF_B1 49152
#define G2_SMEM 65536

__global__ __launch_bounds__(256, 2)
void gemm2_mma_kernel(const __nv_bfloat16* __restrict__ s1b,
                      const __nv_bfloat16* __restrict__ W2b,
                      float* __restrict__ out) {
    extern __shared__ __align__(1024) char smem[];
    const uint32_t sb = smem_u32(smem);
    const int tid = threadIdx.x;
    const int warp = tid >> 5, lane = tid & 31;
    const int g = lane >> 2, tig = lane & 3;
    const int wm = warp >> 2, wn = warp & 3;        // warp tile: 64(m) x 32(n)
    const size_t m0 = (size_t)blockIdx.x * 128;
    const int n0 = blockIdx.y * 128;

    const int ldr = tid >> 1;       // 0..127 (tile row for loads)
    const int ldh = tid & 1;        // half-row (64B)

    float acc[4][4][4];
#pragma unroll
    for (int mf = 0; mf < 4; mf++)
#pragma unroll
        for (int nf = 0; nf < 4; nf++)
#pragma unroll
            for (int q = 0; q < 4; q++) acc[mf][nf][q] = 0.0f;

    const __nv_bfloat16* asrc = s1b + (m0 + ldr) * HPAD + ldh * 32;
    const __nv_bfloat16* bsrc = W2b + (size_t)(n0 + ldr) * KCAT + ldh * 32;
    const uint32_t ldst = swz((uint32_t)(ldr * 128 + ldh * 64));

    // prologue: load chunk 0 (A katom 0 -> A0, B chunk 0 -> B0)
#pragma unroll
    for (int j = 0; j < 4; j++) cpasync16(sb + OFF_A0 + (ldst ^ (j * 16)), asrc + j * 8);
#pragma unroll
    for (int j = 0; j < 4; j++) cpasync16(sb + OFF_B0 + (ldst ^ (j * 16)), bsrc + j * 8);
    asm volatile("cp.async.commit_group;" ::: "memory");

#pragma unroll 1
    for (int c = 0; c < 12; c++) {
        if (c < 11) {
            const int cn = c + 1;
            if (cn % 3 == 0) {
                const uint32_t ab = sb + (((cn / 3) & 1) ? OFF_A1 : OFF_A0);
                const __nv_bfloat16* src = asrc + (cn / 3) * 64;
#pragma unroll
                for (int j = 0; j < 4; j++) cpasync16(ab + (ldst ^ (j * 16)), src + j * 8);
            }
            const uint32_t bb = sb + ((cn & 1) ? OFF_B1 : OFF_B0);
            const __nv_bfloat16* src = bsrc + cn * 64;
#pragma unroll
            for (int j = 0; j < 4; j++) cpasync16(bb + (ldst ^ (j * 16)), src + j * 8);
            asm volatile("cp.async.commit_group;" ::: "memory");
            asm volatile("cp.async.wait_group 1;" ::: "memory");
        } else {
            asm volatile("cp.async.wait_group 0;" ::: "memory");
        }
        __syncthreads();

        const uint32_t ab = sb + ((((c / 3)) & 1) ? OFF_A1 : OFF_A0);
        const uint32_t bb = sb + ((c & 1) ? OFF_B1 : OFF_B0);
#pragma unroll
        for (int ks = 0; ks < 4; ks++) {
            uint32_t afr[4][4];
#pragma unroll
            for (int mf = 0; mf < 4; mf++) {
                uint32_t base = (uint32_t)((wm * 64 + mf * 16 + g) * 128 + ks * 32 + tig * 4);
                afr[mf][0] = lds32(ab + swz(base));
                afr[mf][1] = lds32(ab + swz(base + 8 * 128));
                afr[mf][2] = lds32(ab + swz(base + 16));
                afr[mf][3] = lds32(ab + swz(base + 8 * 128 + 16));
            }
            uint32_t bfr[4][2];
#pragma unroll
            for (int nf = 0; nf < 4; nf++) {
                uint32_t base = (uint32_t)((wn * 32 + nf * 8 + g) * 128 + ks * 32 + tig * 4);
                bfr[nf][0] = lds32(bb + swz(base));
                bfr[nf][1] = lds32(bb + swz(base + 16));
            }
#pragma unroll
            for (int mf = 0; mf < 4; mf++)
#pragma unroll
                for (int nf = 0; nf < 4; nf++)
                    mma_bf16(acc[mf][nf], afr[mf], bfr[nf]);
        }
        __syncthreads();
    }

    // epilogue: raw fp32 store (bias added in LIF scan)
#pragma unroll
    for (int mf = 0; mf < 4; mf++) {
        size_t r0 = (m0 + wm * 64 + mf * 16 + g) * HPAD;
#pragma unroll
        for (int nf = 0; nf < 4; nf++) {
            int col = n0 + wn * 32 + nf * 8 + tig * 2;
            *(float2*)(out + r0 + col) = make_float2(acc[mf][nf][0], acc[mf][nf][1]);
            *(float2*)(out + r0 + 8 * HPAD + col) = make_float2(acc[mf][nf][2], acc[mf][nf][3]);
        }
    }
}

// ================= LIF scans =================
__global__ void lif_scan1_kernel(const float* __restrict__ buf,
                                 __nv_bfloat16* __restrict__ s1b) {
    int lane = blockIdx.x * blockDim.x + threadIdx.x;
    float m = 0.0f;
    size_t idx = lane;
#pragma unroll 8
    for (int t = 0; t < T_STEPS; t++) {
        float cur = buf[idx];
        float r = (m > 1.0f) ? 1.0f : 0.0f;
        m = __fadd_rn(__fadd_rn(__fmul_rn(0.9f, m), cur), -r);
        s1b[idx] = __float2bfloat16((m > 1.0f) ? 1.0f : 0.0f);
        idx += LANES;
    }
}
__global__ void lif_scan2_kernel(float* __restrict__ buf, const float* __restrict__ bias) {
    int lane = blockIdx.x * blockDim.x + threadIdx.x;
    float bv = bias[lane & 255];
    float m = 0.0f;
    size_t idx = lane;
#pragma unroll 8
    for (int t = 0; t < T_STEPS; t++) {
        float cur = __fadd_rn(buf[idx], bv);
        float r = (m > 1.0f) ? 1.0f : 0.0f;
        m = __fadd_rn(__fadd_rn(__fmul_rn(0.9f, m), cur), -r);
        buf[idx] = (m > 1.0f) ? 1.0f : 0.0f;
        idx += LANES;
    }
}

// ---- layer 3 GEMM: warp-per-row dot, N=2, K=250 (padded cols exactly 0) ----
__global__ __launch_bounds__(256)
void gemm3_kernel(const float* __restrict__ S2, const float* __restrict__ W3,
                  const float* __restrict__ b3, float* __restrict__ cur3) {
    __shared__ float w0[HPAD], w1[HPAD];
    int tid = threadIdx.x;
    if (tid < 250) { w0[tid] = W3[tid * 2]; w1[tid] = W3[tid * 2 + 1]; }
    else           { w0[tid] = 0.0f;        w1[tid] = 0.0f; }
    __syncthreads();
    int warp = tid >> 5, lane = tid & 31;
    size_t row = (size_t)blockIdx.x * 8 + warp;
    const float4* p = (const float4*)(S2 + row * HPAD);
    float a0 = 0.0f, a1 = 0.0f;
#pragma unroll
    for (int i = 0; i < 2; i++) {
        float4 v = p[lane * 2 + i];
        int k = (lane * 2 + i) * 4;
        a0 = fmaf(v.x, w0[k], a0); a0 = fmaf(v.y, w0[k + 1], a0);
        a0 = fmaf(v.z, w0[k + 2], a0); a0 = fmaf(v.w, w0[k + 3], a0);
        a1 = fmaf(v.x, w1[k], a1); a1 = fmaf(v.y, w1[k + 1], a1);
        a1 = fmaf(v.z, w1[k + 2], a1); a1 = fmaf(v.w, w1[k + 3], a1);
    }
#pragma unroll
    for (int off = 16; off; off >>= 1) {
        a0 += __shfl_xor_sync(0xffffffffu, a0, off);
        a1 += __shfl_xor_sync(0xffffffffu, a1, off);
    }
    if (lane == 0) {
        cur3[row * 2 + 0] = a0 + b3[0];
        cur3[row * 2 + 1] = a1 + b3[1];
    }
}

__global__ void lif3_kernel(const float* __restrict__ cur3, float* __restrict__ out) {
    int lane = blockIdx.x * blockDim.x + threadIdx.x;  // b*2+o
    float m = 0.0f;
#pragma unroll 8
    for (int t = 0; t < T_STEPS; t++) {
        float cur = cur3[t * 1024 + lane];
        float r = (m > 1.0f) ? 1.0f : 0.0f;
        m = __fadd_rn(__fadd_rn(__fmul_rn(0.9f, m), cur), -r);
        out[t * 1024 + lane] = (m > 1.0f) ? 1.0f : 0.0f;
        out[OUTB + t * 1024 + lane] = m;
    }
}

extern "C" void kernel_launch(void* const* d_in, const int* in_sizes, int n_in,
                              void* d_out, int out_size) {
    const float* x  = (const float*)d_in[0];
    const float* W1 = (const float*)d_in[1];
    const float* b1 = (const float*)d_in[2];
    const float* W2 = (const float*)d_in[3];
    const float* b2 = (const float*)d_in[4];
    const float* W3 = (const float*)d_in[5];
    const float* b3 = (const float*)d_in[6];
    float* out = (float*)d_out;

    float *buf1, *buf2, *cur3, *W1p, *b1p, *b2p;
    __nv_bfloat16 *s1b, *W2b;
    cudaGetSymbolAddress((void**)&buf1, g_buf1);
    cudaGetSymbolAddress((void**)&buf2, g_buf2);
    cudaGetSymbolAddress((void**)&cur3, g_cur3);
    cudaGetSymbolAddress((void**)&W1p, g_W1p);
    cudaGetSymbolAddress((void**)&b1p, g_b1p);
    cudaGetSymbolAddress((void**)&b2p, g_b2p);
    cudaGetSymbolAddress((void**)&s1b, g_s1b);
    cudaGetSymbolAddress((void**)&W2b, g_W2b);

    cudaFuncSetAttribute(gemm2_mma_kernel,
                         cudaFuncAttributeMaxDynamicSharedMemorySize, G2_SMEM);

    prep_kernel<<<128, 256>>>(W1, b1, b2);
    prep_w2b_kernel<<<768, 256>>>(W2);

    // layer 1: cur1 = x @ W1 + b1
    sgemm_kernel<<<dim3(MROWS / BM, HPAD / BN), 256>>>(x, W1p, b1p, buf1, NIN);
    lif_scan1_kernel<<<LANES / 256, 256>>>(buf1, s1b);

    // layer 2: cur2 = s1 @ (W2hi+W2mid+W2lo) via mma.sync; bias folded into scan
    gemm2_mma_kernel<<<dim3(MROWS / 128, 2), 256, G2_SMEM>>>(s1b, W2b, buf2);
    lif_scan2_kernel<<<LANES / 256, 256>>>(buf2, b2p);

    // layer 3
    gemm3_kernel<<<MROWS / 8, 256>>>(buf2, W3, b3, cur3);
    lif3_kernel<<<4, 256>>>(cur3, out);
}

// round 7
// speedup vs baseline: 1.6351x; 1.0431x over previous
#include <cuda_runtime.h>
#include <cuda_bf16.h>
#include <cstdint>

#define T_STEPS 1000
#define BATCH   512
#define NIN     128
#define HPAD    256
#define KCAT    768                   // 3 bf16 splits x 256
#define LANES   (BATCH * HPAD)        // 131072
#define MROWS   (T_STEPS * BATCH)     // 512000
#define OUTB    (T_STEPS * BATCH * 2) // 1024000

// ---- scratch (static device memory; no allocations allowed) ----
__device__ float g_buf1[(size_t)MROWS * HPAD];          // cur1 (fp32)
__device__ __nv_bfloat16 g_s1b[(size_t)MROWS * HPAD];   // s1 spikes bf16
__device__ float g_buf2[(size_t)MROWS * HPAD];          // cur2 raw fp32
__device__ __nv_bfloat16 g_s2b[(size_t)MROWS * HPAD];   // s2 spikes bf16
__device__ float g_cur3[(size_t)MROWS * 2];
__device__ float g_W1p[NIN * HPAD];
__device__ float g_b1p[HPAD];
__device__ float g_b2p[HPAD];
__device__ __nv_bfloat16 g_W2b[HPAD * KCAT];  // [n=256][k'=768], 3-split per katom

// ================= helpers =================
__device__ __forceinline__ uint32_t smem_u32(const void* p) {
    return (uint32_t)__cvta_generic_to_shared(p);
}
__device__ __forceinline__ void cpasync16(uint32_t dst, const void* src) {
    asm volatile("cp.async.cg.shared.global [%0], [%1], 16;" :: "r"(dst), "l"(src));
}
__device__ __forceinline__ uint32_t swz(uint32_t off) { return off ^ ((off >> 3) & 0x70); }
__device__ __forceinline__ void ldsm4(uint32_t* r, uint32_t addr) {
    asm volatile("ldmatrix.sync.aligned.m8n8.x4.shared.b16 {%0,%1,%2,%3}, [%4];"
                 : "=r"(r[0]), "=r"(r[1]), "=r"(r[2]), "=r"(r[3]) : "r"(addr));
}
__device__ __forceinline__ void mma_bf16(float* d, const uint32_t* a, const uint32_t* b) {
    asm volatile(
        "mma.sync.aligned.m16n8k16.row.col.f32.bf16.bf16.f32 "
        "{%0,%1,%2,%3}, {%4,%5,%6,%7}, {%8,%9}, {%0,%1,%2,%3};"
        : "+f"(d[0]), "+f"(d[1]), "+f"(d[2]), "+f"(d[3])
        : "r"(a[0]), "r"(a[1]), "r"(a[2]), "r"(a[3]), "r"(b[0]), "r"(b[1]));
}

// ================= prep kernels =================
__global__ void prep_kernel(const float* __restrict__ W1, const float* __restrict__ b1,
                            const float* __restrict__ b2) {
    int i = blockIdx.x * blockDim.x + threadIdx.x;  // 0..32767
    int k = i >> 8, n = i & 255;
    if (i < NIN * HPAD)
        g_W1p[i] = (n < 250) ? W1[k * 250 + n] : 0.0f;
    if (i < HPAD) {
        g_b1p[i] = (i < 250) ? b1[i] : 0.0f;
        g_b2p[i] = (i < 250) ? b2[i] : 0.0f;
    }
}
// W2b[n][c*64+kk] = split_{c%3}(W2[(c/3)*64+kk][n]), zero-padded
__global__ void prep_w2b_kernel(const float* __restrict__ W2) {
    int id = blockIdx.x * blockDim.x + threadIdx.x;  // 0..196607
    int n = id / KCAT, kp = id % KCAT;
    int c = kp >> 6, kk = kp & 63;
    int katom = c / 3, split = c % 3;
    int k = katom * 64 + kk;
    float w = (k < 250 && n < 250) ? W2[k * 250 + n] : 0.0f;
    __nv_bfloat16 hi = __float2bfloat16(w);
    float r1 = w - __bfloat162float(hi);
    __nv_bfloat16 mid = __float2bfloat16(r1);
    float r2 = r1 - __bfloat162float(mid);
    __nv_bfloat16 lo = __float2bfloat16(r2);
    g_W2b[id] = (split == 0) ? hi : (split == 1) ? mid : lo;
}

// ================= packed f32x2 helpers for layer-1 SGEMM =================
__device__ __forceinline__ void ffma2(unsigned long long& d, unsigned long long a,
                                      unsigned long long b) {
    asm("fma.rn.f32x2 %0, %1, %2, %0;" : "+l"(d) : "l"(a), "l"(b));
}
__device__ __forceinline__ unsigned long long dup2(float v) {
    unsigned long long r;
    unsigned int u = __float_as_uint(v);
    asm("mov.b64 %0, {%1, %1};" : "=l"(r) : "r"(u));
    return r;
}
__device__ __forceinline__ float2 unpack2(unsigned long long v) {
    float2 f;
    asm("mov.b64 {%0, %1}, %2;" : "=f"(f.x), "=f"(f.y) : "l"(v));
    return f;
}

// ---- layer-1 fp32 SGEMM (FFMA2), C[M,256] = A[M,128] @ W[128,256] + bias ----
#define BM 128
#define BN 128
#define BK 16
__global__ __launch_bounds__(256, 2)
void sgemm_kernel(const float* __restrict__ A, const float* __restrict__ W,
                  const float* __restrict__ bias, float* __restrict__ C, int K) {
    __shared__ __align__(16) float As[BK][BM];
    __shared__ __align__(16) float Ws[BK][BN];
    const int tid = threadIdx.x;
    const size_t m0 = (size_t)blockIdx.x * BM;
    const int n0 = blockIdx.y * BN;
    const int tr = tid >> 4, tc = tid & 15;
    const int aRow = tid >> 1, aCol = (tid & 1) * 8;
    const int wRow = tid >> 4, wCol = (tid & 15) * 8;

    unsigned long long acc[8][4];
#pragma unroll
    for (int i = 0; i < 8; i++)
#pragma unroll
        for (int jj = 0; jj < 4; jj++) acc[i][jj] = 0ULL;

    const float* Abase = A + (m0 + aRow) * (size_t)K;
    const float* Wbase = W + (size_t)wRow * HPAD + n0 + wCol;

    for (int k0 = 0; k0 < K; k0 += BK) {
        float4 av0 = *(const float4*)(Abase + k0 + aCol);
        float4 av1 = *(const float4*)(Abase + k0 + aCol + 4);
        As[aCol + 0][aRow] = av0.x; As[aCol + 1][aRow] = av0.y;
        As[aCol + 2][aRow] = av0.z; As[aCol + 3][aRow] = av0.w;
        As[aCol + 4][aRow] = av1.x; As[aCol + 5][aRow] = av1.y;
        As[aCol + 6][aRow] = av1.z; As[aCol + 7][aRow] = av1.w;
        float4 wv0 = *(const float4*)(Wbase + (size_t)k0 * HPAD);
        float4 wv1 = *(const float4*)(Wbase + (size_t)k0 * HPAD + 4);
        *(float4*)(&Ws[wRow][wCol]) = wv0;
        *(float4*)(&Ws[wRow][wCol + 4]) = wv1;
        __syncthreads();
#pragma unroll
        for (int k = 0; k < BK; k++) {
            float ra[8];
            *(float4*)(&ra[0]) = *(const float4*)(&As[k][tr * 8]);
            *(float4*)(&ra[4]) = *(const float4*)(&As[k][tr * 8 + 4]);
            unsigned long long rb[4];
            rb[0] = *(const unsigned long long*)(&Ws[k][tc * 4]);
            rb[1] = *(const unsigned long long*)(&Ws[k][tc * 4 + 2]);
            rb[2] = *(const unsigned long long*)(&Ws[k][64 + tc * 4]);
            rb[3] = *(const unsigned long long*)(&Ws[k][64 + tc * 4 + 2]);
#pragma unroll
            for (int i = 0; i < 8; i++) {
                unsigned long long aa = dup2(ra[i]);
                ffma2(acc[i][0], aa, rb[0]);
                ffma2(acc[i][1], aa, rb[1]);
                ffma2(acc[i][2], aa, rb[2]);
                ffma2(acc[i][3], aa, rb[3]);
            }
        }
        __syncthreads();
    }
    const int nA = n0 + tc * 4, nB = n0 + 64 + tc * 4;
    float4 bvA = *(const float4*)(bias + nA);
    float4 bvB = *(const float4*)(bias + nB);
#pragma unroll
    for (int i = 0; i < 8; i++) {
        size_t rowOff = (m0 + tr * 8 + i) * (size_t)HPAD;
        float2 p0 = unpack2(acc[i][0]), p1 = unpack2(acc[i][1]);
        float2 p2 = unpack2(acc[i][2]), p3 = unpack2(acc[i][3]);
        float4 cA = {p0.x + bvA.x, p0.y + bvA.y, p1.x + bvA.z, p1.y + bvA.w};
        float4 cB = {p2.x + bvB.x, p2.y + bvB.y, p3.x + bvB.z, p3.y + bvB.w};
        *(float4*)(C + rowOff + nA) = cA;
        *(float4*)(C + rowOff + nB) = cB;
    }
}

// ================= layer-2 GEMM via mma.sync bf16 (3-split, K=768) =================
// out[M,256] (raw, no bias) = s1b[M,256] @ W2cat ; grid (4000, 2), 256 thr
#define OFF_A0 0
#define OFF_A1 16384
#define OFF_B0 32768
#define OFF_B1 49152
#define G2_SMEM 65536

__global__ __launch_bounds__(256, 2)
void gemm2_mma_kernel(const __nv_bfloat16* __restrict__ s1b,
                      const __nv_bfloat16* __restrict__ W2b,
                      float* __restrict__ out) {
    extern __shared__ __align__(1024) char smem[];
    const uint32_t sb = smem_u32(smem);
    const int tid = threadIdx.x;
    const int warp = tid >> 5, lane = tid & 31;
    const int g = lane >> 2, tig = lane & 3;
    const int wm = warp >> 2, wn = warp & 3;        // warp tile: 64(m) x 32(n)
    const size_t m0 = (size_t)blockIdx.x * 128;
    const int n0 = blockIdx.y * 128;

    const int ldr = tid >> 1;       // 0..127 (tile row for loads)
    const int ldh = tid & 1;        // half-row (64B)

    // ldmatrix per-lane source offsets (within a tile buffer, pre-swizzle)
    const int arow_l = lane & 15, ahalf = lane >> 4;
    const uint32_t a_off0 = (uint32_t)((wm * 64 + arow_l) * 128 + ahalf * 16);
    const int lane8 = lane & 7, laneg = lane >> 3;
    const uint32_t b_off0 =
        (uint32_t)((wn * 32 + ((laneg & 2) ? 8 : 0) + lane8) * 128 + (laneg & 1) * 16);

    float acc[4][4][4];
#pragma unroll
    for (int mf = 0; mf < 4; mf++)
#pragma unroll
        for (int nf = 0; nf < 4; nf++)
#pragma unroll
            for (int q = 0; q < 4; q++) acc[mf][nf][q] = 0.0f;

    const __nv_bfloat16* asrc = s1b + (m0 + ldr) * HPAD + ldh * 32;
    const __nv_bfloat16* bsrc = W2b + (size_t)(n0 + ldr) * KCAT + ldh * 32;
    const uint32_t ldst = swz((uint32_t)(ldr * 128 + ldh * 64));

    // prologue: load chunk 0 (A katom 0 -> A0, B chunk 0 -> B0)
#pragma unroll
    for (int j = 0; j < 4; j++) cpasync16(sb + OFF_A0 + (ldst ^ (j * 16)), asrc + j * 8);
#pragma unroll
    for (int j = 0; j < 4; j++) cpasync16(sb + OFF_B0 + (ldst ^ (j * 16)), bsrc + j * 8);
    asm volatile("cp.async.commit_group;" ::: "memory");

#pragma unroll 1
    for (int c = 0; c < 12; c++) {
        if (c < 11) {
            const int cn = c + 1;
            if (cn % 3 == 0) {
                const uint32_t ab = sb + (((cn / 3) & 1) ? OFF_A1 : OFF_A0);
                const __nv_bfloat16* src = asrc + (cn / 3) * 64;
#pragma unroll
                for (int j = 0; j < 4; j++) cpasync16(ab + (ldst ^ (j * 16)), src + j * 8);
            }
            const uint32_t bb = sb + ((cn & 1) ? OFF_B1 : OFF_B0);
            const __nv_bfloat16* src = bsrc + cn * 64;
#pragma unroll
            for (int j = 0; j < 4; j++) cpasync16(bb + (ldst ^ (j * 16)), src + j * 8);
            asm volatile("cp.async.commit_group;" ::: "memory");
            asm volatile("cp.async.wait_group 1;" ::: "memory");
        } else {
            asm volatile("cp.async.wait_group 0;" ::: "memory");
        }
        __syncthreads();

        const uint32_t ab = sb + ((((c / 3)) & 1) ? OFF_A1 : OFF_A0);
        const uint32_t bb = sb + ((c & 1) ? OFF_B1 : OFF_B0);
#pragma unroll
        for (int ks = 0; ks < 4; ks++) {
            uint32_t afr[4][4];
#pragma unroll
            for (int mf = 0; mf < 4; mf++)
                ldsm4(afr[mf], ab + swz(a_off0 + (uint32_t)(mf * 16 * 128 + ks * 32)));
            uint32_t bfr[4][2];
            ldsm4(&bfr[0][0], bb + swz(b_off0 + (uint32_t)(ks * 32)));
            ldsm4(&bfr[2][0], bb + swz(b_off0 + (uint32_t)(16 * 128 + ks * 32)));
#pragma unroll
            for (int mf = 0; mf < 4; mf++)
#pragma unroll
                for (int nf = 0; nf < 4; nf++)
                    mma_bf16(acc[mf][nf], afr[mf], bfr[nf]);
        }
        __syncthreads();
    }

    // epilogue: raw fp32 store (bias added in LIF scan)
#pragma unroll
    for (int mf = 0; mf < 4; mf++) {
        size_t r0 = (m0 + wm * 64 + mf * 16 + g) * HPAD;
#pragma unroll
        for (int nf = 0; nf < 4; nf++) {
            int col = n0 + wn * 32 + nf * 8 + tig * 2;
            *(float2*)(out + r0 + col) = make_float2(acc[mf][nf][0], acc[mf][nf][1]);
            *(float2*)(out + r0 + 8 * HPAD + col) = make_float2(acc[mf][nf][2], acc[mf][nf][3]);
        }
    }
}

// ================= LIF scans (2 lanes per thread) =================
__global__ void lif_scan1_kernel(const float* __restrict__ buf,
                                 __nv_bfloat16* __restrict__ s1b) {
    int id = blockIdx.x * blockDim.x + threadIdx.x;  // 0..65535
    float ma = 0.0f, mb = 0.0f;
    size_t idx = (size_t)id * 2;
#pragma unroll 4
    for (int t = 0; t < T_STEPS; t++) {
        float2 cur = *(const float2*)(buf + idx);
        float ra = (ma > 1.0f) ? 1.0f : 0.0f;
        float rb = (mb > 1.0f) ? 1.0f : 0.0f;
        ma = __fadd_rn(__fadd_rn(__fmul_rn(0.9f, ma), cur.x), -ra);
        mb = __fadd_rn(__fadd_rn(__fmul_rn(0.9f, mb), cur.y), -rb);
        __nv_bfloat162 sp;
        sp.x = __float2bfloat16((ma > 1.0f) ? 1.0f : 0.0f);
        sp.y = __float2bfloat16((mb > 1.0f) ? 1.0f : 0.0f);
        *(__nv_bfloat162*)(s1b + idx) = sp;
        idx += LANES;
    }
}
// layer 2: read raw fp32 dot, add bias, write bf16 spikes to s2b
__global__ void lif_scan2_kernel(const float* __restrict__ buf,
                                 const float* __restrict__ bias,
                                 __nv_bfloat16* __restrict__ s2b) {
    int id = blockIdx.x * blockDim.x + threadIdx.x;  // 0..65535
    int c = (id * 2) & 255;
    float bva = bias[c], bvb = bias[c + 1];
    float ma = 0.0f, mb = 0.0f;
    size_t idx = (size_t)id * 2;
#pragma unroll 4
    for (int t = 0; t < T_STEPS; t++) {
        float2 raw = *(const float2*)(buf + idx);
        float ca = __fadd_rn(raw.x, bva);
        float cb = __fadd_rn(raw.y, bvb);
        float ra = (ma > 1.0f) ? 1.0f : 0.0f;
        float rb = (mb > 1.0f) ? 1.0f : 0.0f;
        ma = __fadd_rn(__fadd_rn(__fmul_rn(0.9f, ma), ca), -ra);
        mb = __fadd_rn(__fadd_rn(__fmul_rn(0.9f, mb), cb), -rb);
        __nv_bfloat162 sp;
        sp.x = __float2bfloat16((ma > 1.0f) ? 1.0f : 0.0f);
        sp.y = __float2bfloat16((mb > 1.0f) ? 1.0f : 0.0f);
        *(__nv_bfloat162*)(s2b + idx) = sp;
        idx += LANES;
    }
}

// ---- layer 3 GEMM: warp-per-row dot over bf16 spikes, N=2, K=256 (pad cols = 0) ----
__global__ __launch_bounds__(256)
void gemm3_kernel(const __nv_bfloat16* __restrict__ S2, const float* __restrict__ W3,
                  const float* __restrict__ b3, float* __restrict__ cur3) {
    __shared__ float w0[HPAD], w1[HPAD];
    int tid = threadIdx.x;
    if (tid < 250) { w0[tid] = W3[tid * 2]; w1[tid] = W3[tid * 2 + 1]; }
    else           { w0[tid] = 0.0f;        w1[tid] = 0.0f; }
    __syncthreads();
    int warp = tid >> 5, lane = tid & 31;
    size_t row = (size_t)blockIdx.x * 8 + warp;
    const uint4* p = (const uint4*)(S2 + row * HPAD);
    uint4 v = p[lane];  // 8 bf16 at k = lane*8
    const __nv_bfloat162* h = (const __nv_bfloat162*)&v;
    float a0 = 0.0f, a1 = 0.0f;
    int k0 = lane * 8;
#pragma unroll
    for (int j = 0; j < 4; j++) {
        float2 f = __bfloat1622float2(h[j]);
        int k = k0 + j * 2;
        a0 = fmaf(f.x, w0[k], a0); a0 = fmaf(f.y, w0[k + 1], a0);
        a1 = fmaf(f.x, w1[k], a1); a1 = fmaf(f.y, w1[k + 1], a1);
    }
#pragma unroll
    for (int off = 16; off; off >>= 1) {
        a0 += __shfl_xor_sync(0xffffffffu, a0, off);
        a1 += __shfl_xor_sync(0xffffffffu, a1, off);
    }
    if (lane == 0) {
        cur3[row * 2 + 0] = a0 + b3[0];
        cur3[row * 2 + 1] = a1 + b3[1];
    }
}

__global__ void lif3_kernel(const float* __restrict__ cur3, float* __restrict__ out) {
    int lane = blockIdx.x * blockDim.x + threadIdx.x;  // b*2+o
    float m = 0.0f;
#pragma unroll 8
    for (int t = 0; t < T_STEPS; t++) {
        float cur = cur3[t * 1024 + lane];
        float r = (m > 1.0f) ? 1.0f : 0.0f;
        m = __fadd_rn(__fadd_rn(__fmul_rn(0.9f, m), cur), -r);
        out[t * 1024 + lane] = (m > 1.0f) ? 1.0f : 0.0f;
        out[OUTB + t * 1024 + lane] = m;
    }
}

extern "C" void kernel_launch(void* const* d_in, const int* in_sizes, int n_in,
                              void* d_out, int out_size) {
    const float* x  = (const float*)d_in[0];
    const float* W1 = (const float*)d_in[1];
    const float* b1 = (const float*)d_in[2];
    const float* W2 = (const float*)d_in[3];
    const float* b2 = (const float*)d_in[4];
    const float* W3 = (const float*)d_in[5];
    const float* b3 = (const float*)d_in[6];
    float* out = (float*)d_out;

    float *buf1, *buf2, *cur3, *W1p, *b1p, *b2p;
    __nv_bfloat16 *s1b, *s2b, *W2b;
    cudaGetSymbolAddress((void**)&buf1, g_buf1);
    cudaGetSymbolAddress((void**)&buf2, g_buf2);
    cudaGetSymbolAddress((void**)&cur3, g_cur3);
    cudaGetSymbolAddress((void**)&W1p, g_W1p);
    cudaGetSymbolAddress((void**)&b1p, g_b1p);
    cudaGetSymbolAddress((void**)&b2p, g_b2p);
    cudaGetSymbolAddress((void**)&s1b, g_s1b);
    cudaGetSymbolAddress((void**)&s2b, g_s2b);
    cudaGetSymbolAddress((void**)&W2b, g_W2b);

    cudaFuncSetAttribute(gemm2_mma_kernel,
                         cudaFuncAttributeMaxDynamicSharedMemorySize, G2_SMEM);

    prep_kernel<<<128, 256>>>(W1, b1, b2);
    prep_w2b_kernel<<<768, 256>>>(W2);

    // layer 1: cur1 = x @ W1 + b1
    sgemm_kernel<<<dim3(MROWS / BM, HPAD / BN), 256>>>(x, W1p, b1p, buf1, NIN);
    lif_scan1_kernel<<<LANES / 512, 256>>>(buf1, s1b);

    // layer 2: cur2 = s1 @ (W2hi+W2mid+W2lo) via mma.sync; bias folded into scan
    gemm2_mma_kernel<<<dim3(MROWS / 128, 2), 256, G2_SMEM>>>(s1b, W2b, buf2);
    lif_scan2_kernel<<<LANES / 512, 256>>>(buf2, b2p, s2b);

    // layer 3
    gemm3_kernel<<<MROWS / 8, 256>>>(s2b, W3, b3, cur3);
    lif3_kernel<<<4, 256>>>(cur3, out);
}

// round 8
// speedup vs baseline: 1.8967x; 1.1600x over previous
#include <cuda_runtime.h>
#include <cuda_fp16.h>
#include <cstdint>

#define T_STEPS 1000
#define BATCH   512
#define NIN     128
#define HPAD    256
#define KCAT2   512                   // 2 fp16 splits x 256
#define LANES   (BATCH * HPAD)        // 131072
#define MROWS   (T_STEPS * BATCH)     // 512000
#define OUTB    (T_STEPS * BATCH * 2) // 1024000

// ---- scratch (static device memory; no allocations allowed) ----
__device__ float g_buf1[(size_t)MROWS * HPAD];   // cur1 (fp32)
__device__ __half g_s1h[(size_t)MROWS * HPAD];   // s1 spikes fp16
__device__ float g_buf2[(size_t)MROWS * HPAD];   // cur2 raw fp32
__device__ __half g_s2h[(size_t)MROWS * HPAD];   // s2 spikes fp16
__device__ float g_cur3[(size_t)MROWS * 2];
__device__ float g_W1p[NIN * HPAD];
__device__ float g_b1p[HPAD];
__device__ float g_b2p[HPAD];
__device__ __half g_W2h[HPAD * KCAT2];  // [n=256][k'=512], 2-split fp16 per katom

// ================= helpers =================
__device__ __forceinline__ uint32_t smem_u32(const void* p) {
    return (uint32_t)__cvta_generic_to_shared(p);
}
__device__ __forceinline__ void cpasync16(uint32_t dst, const void* src) {
    asm volatile("cp.async.cg.shared.global [%0], [%1], 16;" :: "r"(dst), "l"(src));
}
__device__ __forceinline__ uint32_t swz(uint32_t off) { return off ^ ((off >> 3) & 0x70); }
__device__ __forceinline__ void ldsm4(uint32_t* r, uint32_t addr) {
    asm volatile("ldmatrix.sync.aligned.m8n8.x4.shared.b16 {%0,%1,%2,%3}, [%4];"
                 : "=r"(r[0]), "=r"(r[1]), "=r"(r[2]), "=r"(r[3]) : "r"(addr));
}
__device__ __forceinline__ void mma_f16(float* d, const uint32_t* a, const uint32_t* b) {
    asm volatile(
        "mma.sync.aligned.m16n8k16.row.col.f32.f16.f16.f32 "
        "{%0,%1,%2,%3}, {%4,%5,%6,%7}, {%8,%9}, {%0,%1,%2,%3};"
        : "+f"(d[0]), "+f"(d[1]), "+f"(d[2]), "+f"(d[3])
        : "r"(a[0]), "r"(a[1]), "r"(a[2]), "r"(a[3]), "r"(b[0]), "r"(b[1]));
}

// ================= prep kernels =================
__global__ void prep_kernel(const float* __restrict__ W1, const float* __restrict__ b1,
                            const float* __restrict__ b2) {
    int i = blockIdx.x * blockDim.x + threadIdx.x;  // 0..32767
    int k = i >> 8, n = i & 255;
    if (i < NIN * HPAD)
        g_W1p[i] = (n < 250) ? W1[k * 250 + n] : 0.0f;
    if (i < HPAD) {
        g_b1p[i] = (i < 250) ? b1[i] : 0.0f;
        g_b2p[i] = (i < 250) ? b2[i] : 0.0f;
    }
}
// W2h[n][c*64+kk] = split_{c%2}(W2[(c/2)*64+kk][n]); exact 2-term fp16 split
__global__ void prep_w2h_kernel(const float* __restrict__ W2) {
    int id = blockIdx.x * blockDim.x + threadIdx.x;  // 0..131071
    int n = id / KCAT2, kp = id % KCAT2;
    int c = kp >> 6, kk = kp & 63;
    int katom = c >> 1, split = c & 1;
    int k = katom * 64 + kk;
    float w = (k < 250 && n < 250) ? W2[k * 250 + n] : 0.0f;
    __half hi = __float2half_rn(w);
    float r1 = w - __half2float(hi);
    __half lo = __float2half_rn(r1);
    g_W2h[id] = (split == 0) ? hi : lo;
}

// ================= packed f32x2 helpers for layer-1 SGEMM =================
__device__ __forceinline__ void ffma2(unsigned long long& d, unsigned long long a,
                                      unsigned long long b) {
    asm("fma.rn.f32x2 %0, %1, %2, %0;" : "+l"(d) : "l"(a), "l"(b));
}
__device__ __forceinline__ unsigned long long dup2(float v) {
    unsigned long long r;
    unsigned int u = __float_as_uint(v);
    asm("mov.b64 %0, {%1, %1};" : "=l"(r) : "r"(u));
    return r;
}
__device__ __forceinline__ float2 unpack2(unsigned long long v) {
    float2 f;
    asm("mov.b64 {%0, %1}, %2;" : "=f"(f.x), "=f"(f.y) : "l"(v));
    return f;
}

// ---- layer-1 fp32 SGEMM (FFMA2), C[M,256] = A[M,128] @ W[128,256] + bias ----
#define BM 128
#define BN 128
#define BK 16
__global__ __launch_bounds__(256, 2)
void sgemm_kernel(const float* __restrict__ A, const float* __restrict__ W,
                  const float* __restrict__ bias, float* __restrict__ C, int K) {
    __shared__ __align__(16) float As[BK][BM];
    __shared__ __align__(16) float Ws[BK][BN];
    const int tid = threadIdx.x;
    const size_t m0 = (size_t)blockIdx.x * BM;
    const int n0 = blockIdx.y * BN;
    const int tr = tid >> 4, tc = tid & 15;
    const int aRow = tid >> 1, aCol = (tid & 1) * 8;
    const int wRow = tid >> 4, wCol = (tid & 15) * 8;

    unsigned long long acc[8][4];
#pragma unroll
    for (int i = 0; i < 8; i++)
#pragma unroll
        for (int jj = 0; jj < 4; jj++) acc[i][jj] = 0ULL;

    const float* Abase = A + (m0 + aRow) * (size_t)K;
    const float* Wbase = W + (size_t)wRow * HPAD + n0 + wCol;

    for (int k0 = 0; k0 < K; k0 += BK) {
        float4 av0 = *(const float4*)(Abase + k0 + aCol);
        float4 av1 = *(const float4*)(Abase + k0 + aCol + 4);
        As[aCol + 0][aRow] = av0.x; As[aCol + 1][aRow] = av0.y;
        As[aCol + 2][aRow] = av0.z; As[aCol + 3][aRow] = av0.w;
        As[aCol + 4][aRow] = av1.x; As[aCol + 5][aRow] = av1.y;
        As[aCol + 6][aRow] = av1.z; As[aCol + 7][aRow] = av1.w;
        float4 wv0 = *(const float4*)(Wbase + (size_t)k0 * HPAD);
        float4 wv1 = *(const float4*)(Wbase + (size_t)k0 * HPAD + 4);
        *(float4*)(&Ws[wRow][wCol]) = wv0;
        *(float4*)(&Ws[wRow][wCol + 4]) = wv1;
        __syncthreads();
#pragma unroll
        for (int k = 0; k < BK; k++) {
            float ra[8];
            *(float4*)(&ra[0]) = *(const float4*)(&As[k][tr * 8]);
            *(float4*)(&ra[4]) = *(const float4*)(&As[k][tr * 8 + 4]);
            unsigned long long rb[4];
            rb[0] = *(const unsigned long long*)(&Ws[k][tc * 4]);
            rb[1] = *(const unsigned long long*)(&Ws[k][tc * 4 + 2]);
            rb[2] = *(const unsigned long long*)(&Ws[k][64 + tc * 4]);
            rb[3] = *(const unsigned long long*)(&Ws[k][64 + tc * 4 + 2]);
#pragma unroll
            for (int i = 0; i < 8; i++) {
                unsigned long long aa = dup2(ra[i]);
                ffma2(acc[i][0], aa, rb[0]);
                ffma2(acc[i][1], aa, rb[1]);
                ffma2(acc[i][2], aa, rb[2]);
                ffma2(acc[i][3], aa, rb[3]);
            }
        }
        __syncthreads();
    }
    const int nA = n0 + tc * 4, nB = n0 + 64 + tc * 4;
    float4 bvA = *(const float4*)(bias + nA);
    float4 bvB = *(const float4*)(bias + nB);
#pragma unroll
    for (int i = 0; i < 8; i++) {
        size_t rowOff = (m0 + tr * 8 + i) * (size_t)HPAD;
        float2 p0 = unpack2(acc[i][0]), p1 = unpack2(acc[i][1]);
        float2 p2 = unpack2(acc[i][2]), p3 = unpack2(acc[i][3]);
        float4 cA = {p0.x + bvA.x, p0.y + bvA.y, p1.x + bvA.z, p1.y + bvA.w};
        float4 cB = {p2.x + bvB.x, p2.y + bvB.y, p3.x + bvB.z, p3.y + bvB.w};
        *(float4*)(C + rowOff + nA) = cA;
        *(float4*)(C + rowOff + nB) = cB;
    }
}

// ================= layer-2 GEMM via mma.sync fp16 (2-split, K=512) =================
// out[M,256] (raw, no bias) = s1h[M,256] @ W2cat ; grid (4000, 2), 256 thr
#define OFF_A0 0
#define OFF_A1 16384
#define OFF_B0 32768
#define OFF_B1 49152
#define G2_SMEM 65536
#define NCHUNK 8

__global__ __launch_bounds__(256, 2)
void gemm2_mma_kernel(const __half* __restrict__ s1h,
                      const __half* __restrict__ W2h,
                      float* __restrict__ out) {
    extern __shared__ __align__(1024) char smem[];
    const uint32_t sb = smem_u32(smem);
    const int tid = threadIdx.x;
    const int warp = tid >> 5, lane = tid & 31;
    const int g = lane >> 2, tig = lane & 3;
    const int wm = warp >> 2, wn = warp & 3;        // warp tile: 64(m) x 32(n)
    const size_t m0 = (size_t)blockIdx.x * 128;
    const int n0 = blockIdx.y * 128;

    const int ldr = tid >> 1;       // 0..127 (tile row for loads)
    const int ldh = tid & 1;        // half-row (64B)

    // ldmatrix per-lane source offsets (within a tile buffer, pre-swizzle)
    const int arow_l = lane & 15, ahalf = lane >> 4;
    const uint32_t a_off0 = (uint32_t)((wm * 64 + arow_l) * 128 + ahalf * 16);
    const int lane8 = lane & 7, laneg = lane >> 3;
    const uint32_t b_off0 =
        (uint32_t)((wn * 32 + ((laneg & 2) ? 8 : 0) + lane8) * 128 + (laneg & 1) * 16);

    float acc[4][4][4];
#pragma unroll
    for (int mf = 0; mf < 4; mf++)
#pragma unroll
        for (int nf = 0; nf < 4; nf++)
#pragma unroll
            for (int q = 0; q < 4; q++) acc[mf][nf][q] = 0.0f;

    const __half* asrc = s1h + (m0 + ldr) * HPAD + ldh * 32;
    const __half* bsrc = W2h + (size_t)(n0 + ldr) * KCAT2 + ldh * 32;
    const uint32_t ldst = swz((uint32_t)(ldr * 128 + ldh * 64));

    // prologue: load chunk 0 (A katom 0 -> A0, B chunk 0 -> B0)
#pragma unroll
    for (int j = 0; j < 4; j++) cpasync16(sb + OFF_A0 + (ldst ^ (j * 16)), asrc + j * 8);
#pragma unroll
    for (int j = 0; j < 4; j++) cpasync16(sb + OFF_B0 + (ldst ^ (j * 16)), bsrc + j * 8);
    asm volatile("cp.async.commit_group;" ::: "memory");

#pragma unroll 1
    for (int c = 0; c < NCHUNK; c++) {
        if (c < NCHUNK - 1) {
            const int cn = c + 1;
            if ((cn & 1) == 0) {  // new katom -> load A
                const uint32_t ab = sb + (((cn >> 1) & 1) ? OFF_A1 : OFF_A0);
                const __half* src = asrc + (cn >> 1) * 64;
#pragma unroll
                for (int j = 0; j < 4; j++) cpasync16(ab + (ldst ^ (j * 16)), src + j * 8);
            }
            const uint32_t bb = sb + ((cn & 1) ? OFF_B1 : OFF_B0);
            const __half* src = bsrc + cn * 64;
#pragma unroll
            for (int j = 0; j < 4; j++) cpasync16(bb + (ldst ^ (j * 16)), src + j * 8);
            asm volatile("cp.async.commit_group;" ::: "memory");
            asm volatile("cp.async.wait_group 1;" ::: "memory");
        } else {
            asm volatile("cp.async.wait_group 0;" ::: "memory");
        }
        __syncthreads();

        const uint32_t ab = sb + (((c >> 1) & 1) ? OFF_A1 : OFF_A0);
        const uint32_t bb = sb + ((c & 1) ? OFF_B1 : OFF_B0);
#pragma unroll
        for (int ks = 0; ks < 4; ks++) {
            uint32_t afr[4][4];
#pragma unroll
            for (int mf = 0; mf < 4; mf++)
                ldsm4(afr[mf], ab + swz(a_off0 + (uint32_t)(mf * 16 * 128 + ks * 32)));
            uint32_t bfr[4][2];
            ldsm4(&bfr[0][0], bb + swz(b_off0 + (uint32_t)(ks * 32)));
            ldsm4(&bfr[2][0], bb + swz(b_off0 + (uint32_t)(16 * 128 + ks * 32)));
#pragma unroll
            for (int mf = 0; mf < 4; mf++)
#pragma unroll
                for (int nf = 0; nf < 4; nf++)
                    mma_f16(acc[mf][nf], afr[mf], bfr[nf]);
        }
        __syncthreads();
    }

    // epilogue: raw fp32 store (bias added in LIF scan)
#pragma unroll
    for (int mf = 0; mf < 4; mf++) {
        size_t r0 = (m0 + wm * 64 + mf * 16 + g) * HPAD;
#pragma unroll
        for (int nf = 0; nf < 4; nf++) {
            int col = n0 + wn * 32 + nf * 8 + tig * 2;
            *(float2*)(out + r0 + col) = make_float2(acc[mf][nf][0], acc[mf][nf][1]);
            *(float2*)(out + r0 + 8 * HPAD + col) = make_float2(acc[mf][nf][2], acc[mf][nf][3]);
        }
    }
}

// ================= LIF scans (1 lane per thread) =================
__global__ void lif_scan1_kernel(const float* __restrict__ buf,
                                 __half* __restrict__ s1h) {
    int lane = blockIdx.x * blockDim.x + threadIdx.x;  // 0..131071
    float m = 0.0f;
    size_t idx = lane;
#pragma unroll 8
    for (int t = 0; t < T_STEPS; t++) {
        float cur = buf[idx];
        float r = (m > 1.0f) ? 1.0f : 0.0f;
        m = __fadd_rn(__fadd_rn(__fmul_rn(0.9f, m), cur), -r);
        s1h[idx] = __float2half((m > 1.0f) ? 1.0f : 0.0f);
        idx += LANES;
    }
}
// layer 2: read raw fp32 dot, add bias, write fp16 spikes
__global__ void lif_scan2_kernel(const float* __restrict__ buf,
                                 const float* __restrict__ bias,
                                 __half* __restrict__ s2h) {
    int lane = blockIdx.x * blockDim.x + threadIdx.x;
    float bv = bias[lane & 255];
    float m = 0.0f;
    size_t idx = lane;
#pragma unroll 8
    for (int t = 0; t < T_STEPS; t++) {
        float cur = __fadd_rn(buf[idx], bv);
        float r = (m > 1.0f) ? 1.0f : 0.0f;
        m = __fadd_rn(__fadd_rn(__fmul_rn(0.9f, m), cur), -r);
        s2h[idx] = __float2half((m > 1.0f) ? 1.0f : 0.0f);
        idx += LANES;
    }
}

// ---- layer 3 GEMM: warp-per-row dot over fp16 spikes, N=2, K=256 (pad cols = 0) ----
__global__ __launch_bounds__(256)
void gemm3_kernel(const __half* __restrict__ S2, const float* __restrict__ W3,
                  const float* __restrict__ b3, float* __restrict__ cur3) {
    __shared__ float w0[HPAD], w1[HPAD];
    int tid = threadIdx.x;
    if (tid < 250) { w0[tid] = W3[tid * 2]; w1[tid] = W3[tid * 2 + 1]; }
    else           { w0[tid] = 0.0f;        w1[tid] = 0.0f; }
    __syncthreads();
    int warp = tid >> 5, lane = tid & 31;
    size_t row = (size_t)blockIdx.x * 8 + warp;
    const uint4* p = (const uint4*)(S2 + row * HPAD);
    uint4 v = p[lane];  // 8 fp16 at k = lane*8
    const __half2* h = (const __half2*)&v;
    float a0 = 0.0f, a1 = 0.0f;
    int k0 = lane * 8;
#pragma unroll
    for (int j = 0; j < 4; j++) {
        float2 f = __half22float2(h[j]);
        int k = k0 + j * 2;
        a0 = fmaf(f.x, w0[k], a0); a0 = fmaf(f.y, w0[k + 1], a0);
        a1 = fmaf(f.x, w1[k], a1); a1 = fmaf(f.y, w1[k + 1], a1);
    }
#pragma unroll
    for (int off = 16; off; off >>= 1) {
        a0 += __shfl_xor_sync(0xffffffffu, a0, off);
        a1 += __shfl_xor_sync(0xffffffffu, a1, off);
    }
    if (lane == 0) {
        cur3[row * 2 + 0] = a0 + b3[0];
        cur3[row * 2 + 1] = a1 + b3[1];
    }
}

__global__ void lif3_kernel(const float* __restrict__ cur3, float* __restrict__ out) {
    int lane = blockIdx.x * blockDim.x + threadIdx.x;  // b*2+o
    float m = 0.0f;
#pragma unroll 8
    for (int t = 0; t < T_STEPS; t++) {
        float cur = cur3[t * 1024 + lane];
        float r = (m > 1.0f) ? 1.0f : 0.0f;
        m = __fadd_rn(__fadd_rn(__fmul_rn(0.9f, m), cur), -r);
        out[t * 1024 + lane] = (m > 1.0f) ? 1.0f : 0.0f;
        out[OUTB + t * 1024 + lane] = m;
    }
}

extern "C" void kernel_launch(void* const* d_in, const int* in_sizes, int n_in,
                              void* d_out, int out_size) {
    const float* x  = (const float*)d_in[0];
    const float* W1 = (const float*)d_in[1];
    const float* b1 = (const float*)d_in[2];
    const float* W2 = (const float*)d_in[3];
    const float* b2 = (const float*)d_in[4];
    const float* W3 = (const float*)d_in[5];
    const float* b3 = (const float*)d_in[6];
    float* out = (float*)d_out;

    float *buf1, *buf2, *cur3, *W1p, *b1p, *b2p;
    __half *s1h, *s2h, *W2h;
    cudaGetSymbolAddress((void**)&buf1, g_buf1);
    cudaGetSymbolAddress((void**)&buf2, g_buf2);
    cudaGetSymbolAddress((void**)&cur3, g_cur3);
    cudaGetSymbolAddress((void**)&W1p, g_W1p);
    cudaGetSymbolAddress((void**)&b1p, g_b1p);
    cudaGetSymbolAddress((void**)&b2p, g_b2p);
    cudaGetSymbolAddress((void**)&s1h, g_s1h);
    cudaGetSymbolAddress((void**)&s2h, g_s2h);
    cudaGetSymbolAddress((void**)&W2h, g_W2h);

    cudaFuncSetAttribute(gemm2_mma_kernel,
                         cudaFuncAttributeMaxDynamicSharedMemorySize, G2_SMEM);

    prep_kernel<<<128, 256>>>(W1, b1, b2);
    prep_w2h_kernel<<<512, 256>>>(W2);

    // layer 1: cur1 = x @ W1 + b1
    sgemm_kernel<<<dim3(MROWS / BM, HPAD / BN), 256>>>(x, W1p, b1p, buf1, NIN);
    lif_scan1_kernel<<<LANES / 256, 256>>>(buf1, s1h);

    // layer 2: cur2 = s1 @ (W2hi + W2lo) via fp16 mma.sync; bias folded into scan
    gemm2_mma_kernel<<<dim3(MROWS / 128, 2), 256, G2_SMEM>>>(s1h, W2h, buf2);
    lif_scan2_kernel<<<LANES / 256, 256>>>(buf2, b2p, s2h);

    // layer 3
    gemm3_kernel<<<MROWS / 8, 256>>>(s2h, W3, b3, cur3);
    lif3_kernel<<<4, 256>>>(cur3, out);
}